// round 14
// baseline (speedup 1.0000x reference)
#include <cuda_runtime.h>
#include <math.h>

// Problem constants
#define NB    64
#define NH    512
#define NW    512
#define NPTS  200

#define EPS_LO 0.4999f
#define EPS_HI 0.5001f
#define ROWCAP 8          // borderline values stored per row (true count kept separately)
#define BPB    64         // kA blocks per batch

// bare MUFU.EX2 (no library fix-up code)
__device__ __forceinline__ float ex2_approx(float x) {
    float y;
    asm("ex2.approx.f32 %0, %1;" : "=f"(y) : "f"(x));
    return y;
}

// ---------------- scratch (device globals; every slot written every call,
// so no init kernel and no resets are needed) ----------------
__device__ float  g_pmn[NB][BPB];
__device__ float  g_pmx[NB][BPB];
// g_cnt[half][batch][row]: half 0 = cols [0,256), half 1 = cols [256,512)
__device__ float  g_cnt[2][NB][NH];
__device__ int    g_blcnt[NB][NH];          // true borderline count per row
__device__ float  g_blv[NB][NH][ROWCAP];    // packed: +v -> half 0, -v -> half 1

// ---------------- KA: fused single pass (DRAM-bound, atomic-free) --------
// One warp per row, 8 warps/block, 64 blocks/batch, grid 4096.
// Streaming loads (__ldcv) — data is read once, don't churn L2.
__global__ void __launch_bounds__(256, 8)
kA_pass(const float4* __restrict__ in) {
    int gwarp = (blockIdx.x * blockDim.x + threadIdx.x) >> 5;  // 0..32767
    int lane  = threadIdx.x & 31;
    int b   = gwarp >> 9;
    int row = gwarp & 511;

    const float4* p = in + ((size_t)(b * NH + row)) * 256;  // 256 float4/row

    // front-batched streaming loads: 8 independent LDG.128.CV in flight
    float a[16];
#pragma unroll
    for (int i = 0; i < 8; i++) {
        float4 t = __ldcv(p + lane + i * 32);
        a[2 * i]     = t.y;            // channel-1 of pixel 2k
        a[2 * i + 1] = t.w;            // channel-1 of pixel 2k+1
    }

    float mn = 1e30f, mx = -1e30f;
    float md = 1e30f;                  // min |v - 0.5|
    unsigned cL = 0, cR = 0;
#pragma unroll
    for (int i = 0; i < 16; i++) {
        float v = a[i];
        mn = fminf(mn, v);
        mx = fmaxf(mx, v);
        md = fminf(md, fabsf(v - 0.5f));
        unsigned pred = (unsigned)(v > EPS_LO);
        if (i < 8) cL += pred; else cR += pred;   // idx <8 -> cols [0,256)
    }

    // borderline capture, guarded: window (0.4999,0.5001] implies
    // |v-0.5| <= 1.0002e-4 < 1.1e-4, so the guard is a strict superset.
    if (__ballot_sync(0xffffffffu, md <= 1.1e-4f)) {
        int base = 0;
#pragma unroll
        for (int i = 0; i < 16; i++) {
            float v = a[i];
            bool bl = (v > EPS_LO) && (v <= EPS_HI);
            unsigned mask = __ballot_sync(0xffffffffu, bl);
            if (bl) {
                int idx = base + __popc(mask & ((1u << lane) - 1u));
                if (idx < ROWCAP)
                    g_blv[b][row][idx] = (i < 8) ? v : -v;   // sign encodes half
            }
            base += __popc(mask);
        }
        if (lane == 0) g_blcnt[b][row] = base;
    } else {
        if (lane == 0) g_blcnt[b][row] = 0;
    }

    cL = __reduce_add_sync(0xffffffffu, cL);
    cR = __reduce_add_sync(0xffffffffu, cR);
    if (lane == 0) {
        g_cnt[0][b][row] = (float)cL;
        g_cnt[1][b][row] = (float)cR;
    }

    // block-level min/max partials (no atomics)
#pragma unroll
    for (int o = 16; o; o >>= 1) {
        mn = fminf(mn, __shfl_xor_sync(0xffffffffu, mn, o));
        mx = fmaxf(mx, __shfl_xor_sync(0xffffffffu, mx, o));
    }
    __shared__ float smn[8], smx[8];
    int w = threadIdx.x >> 5;
    if (lane == 0) { smn[w] = mn; smx[w] = mx; }
    __syncthreads();
    if (threadIdx.x == 0) {
#pragma unroll
        for (int i = 1; i < 8; i++) { mn = fminf(mn, smn[i]); mx = fmaxf(mx, smx[i]); }
        g_pmn[b][blockIdx.x & 63] = mn;
        g_pmx[b][blockIdx.x & 63] = mx;
    }
}

// ---------------- K3: merged prelude + Gaussian resampling ----------------
// grid 1024 (= unit*8 + 32-point group), block 256 (8 warps).
// Each warp = one sub (warp-uniform -> SMEM broadcasts), covering 64 rows
// for its block's 32 points; 8 partial sums combined in SMEM.
__global__ void __launch_bounds__(256)
k3_merged(const float4* __restrict__ in, float* __restrict__ out) {
    const float TWO_PI = 6.283185307179586f;
    const float TT0    = (float)(M_PI / 2.0);
    const float DT     = (float)(M_PI / 200.0);
    const float SQK    = 12.011224469026914f;  // sqrt(100 * log2(e))

    int unit = blockIdx.x >> 3;
    int grp  = blockIdx.x & 7;         // 32-point group (slots grp*32..+31)
    int b = unit >> 1, c = unit & 1;
    int tid = threadIdx.x;

    __shared__ float  s_x1[NH];
    __shared__ float2 s_rt[NH];        // (tt, r); read as float4 in hot loop
    __shared__ float  s_red[16];
    __shared__ int    s_ovf;
    __shared__ float  s_num[8][32];
    __shared__ float  s_den[8][32];

    // ---- prelude (256 threads; rows tid and tid+256) ----
    if (tid == 0) s_ovf = 0;
    if (tid < BPB) {
        float v = g_pmn[b][tid];
#pragma unroll
        for (int o = 16; o; o >>= 1) v = fminf(v, __shfl_xor_sync(0xffffffffu, v, o));
        if ((tid & 31) == 0) s_red[tid >> 5] = v;               // slots 0,1
    } else if (tid < 2 * BPB) {
        float v = g_pmx[b][tid - BPB];
#pragma unroll
        for (int o = 16; o; o >>= 1) v = fmaxf(v, __shfl_xor_sync(0xffffffffu, v, o));
        if ((tid & 31) == 0) s_red[2 + ((tid - BPB) >> 5)] = v; // slots 2,3
    }
    s_x1[tid]       = g_cnt[c][b][tid];
    s_x1[tid + 256] = g_cnt[c][b][tid + 256];
    int bl0 = g_blcnt[b][tid];
    int bl1 = g_blcnt[b][tid + 256];
    if (bl0 > ROWCAP || bl1 > ROWCAP) s_ovf = 1;  // benign race
    __syncthreads();

    float mn = fminf(s_red[0], s_red[1]);
    float mx = fmaxf(s_red[2], s_red[3]);
    float h  = 0.5f * (mx - mn);       // exact predicate: (v - mn) > h

    // Window validity: all v <= EPS_LO must fail, all v > EPS_HI must pass.
    bool ok = ((EPS_LO - mn) <= h) && ((EPS_HI - mn) > h) && (s_ovf == 0);
    if (ok) {
        // exact correction; each thread owns rows tid and tid+256 -> no atomics
#pragma unroll
        for (int k = 0; k < 2; k++) {
            int row = tid + k * 256;
            int blc = k ? bl1 : bl0;
            float corr = 0.f;
            for (int j = 0; j < blc; j++) {
                float pv = g_blv[b][row][j];
                int   half = pv < 0.0f;
                float v = fabsf(pv);
                if (half == c && !((v - mn) > h)) corr += 1.0f;
            }
            s_x1[row] -= corr;
        }
    } else {
        // never-expected exact fallback: full recount of this (b, c) half
        __syncthreads();
        int w = tid >> 5, lane = tid & 31;
        for (int row = w; row < NH; row += 8) {
            const float4* p = in + ((size_t)(b * NH + row)) * 256 + c * 128;
            unsigned cnt = 0;
#pragma unroll
            for (int k = 0; k < 4; k++) {
                float4 v = p[lane + k * 32];
                cnt += (unsigned)((v.y - mn) > h) + (unsigned)((v.w - mn) > h);
            }
            cnt = __reduce_add_sync(0xffffffffu, cnt);
            if (lane == 0) s_x1[row] = (float)cnt;
        }
    }
    __syncthreads();

    // bounds: ythtop = 256 - sum(xa[0:256]), ythbottom = 256 + sum(xa[256:512])
    {
        float st = fminf(s_x1[tid], 1.0f);
        float sb = fminf(s_x1[tid + 256], 1.0f);
#pragma unroll
        for (int o = 16; o; o >>= 1) {
            st += __shfl_xor_sync(0xffffffffu, st, o);
            sb += __shfl_xor_sync(0xffffffffu, sb, o);
        }
        if ((tid & 31) == 0) { s_red[tid >> 5] = st; s_red[8 + (tid >> 5)] = sb; }
    }
    __syncthreads();
    float top = 256.0f, bot = 256.0f;
#pragma unroll
    for (int i = 0; i < 8; i++) { top -= s_red[i]; bot += s_red[8 + i]; }

    // polar transform (fix_radians -> [0, 2pi))
#pragma unroll
    for (int k = 0; k < 2; k++) {
        int row = tid + k * 256;
        float x1 = s_x1[row];
        float y1 = fminf(fmaxf((float)row, top), bot);
        float yc = y1 - 256.0f;
        float xc = -x1;
        float r  = sqrtf(xc * xc + yc * yc);
        float tt = atan2f(yc, xc);
        if (tt < 0.0f) tt += TWO_PI;
        s_rt[row] = make_float2(tt, r);
    }
    __syncthreads();

    // ---- Gaussian hot loop ----
    // Range proof: xc <= 0 -> tt in [pi/2, 3pi/2]; ttn in [pi/2, 3pi/2) ->
    //   d in (-pi, pi]: no wrap needed; +-2pi period candidates give ~0.
    // Clamp dropped: reference clamps d^2>1 to exp(-100) ~ 3.7e-44 ~ 0.
    // Weight: exp(-100 d^2) = ex2(-(S*tt - S*ttn)^2), S = sqrt(100*log2(e)).
    int np  = tid & 31;                // point within this group
    int sub = tid >> 5;                // 0..7, warp-uniform
    int n   = grp * 32 + np;           // global point-slot (real < 200)
    float ttnS = (TT0 + (float)n * DT) * SQK;
    float num = 0.f, den = 0.f;
    const float4* rt4 = (const float4*)s_rt;   // (tt0, r0, tt1, r1)
    int base4 = sub << 5;              // 32 float4 per sub-range (64 rows)
#pragma unroll 8
    for (int m = 0; m < 32; m++) {
        float4 v = rt4[base4 + m];
        float t0 = fmaf(v.x, SQK, -ttnS);
        float w0 = ex2_approx(-t0 * t0);
        den += w0;
        num = fmaf(w0, v.y, num);
        float t1 = fmaf(v.z, SQK, -ttnS);
        float w1 = ex2_approx(-t1 * t1);
        den += w1;
        num = fmaf(w1, v.w, num);
    }
    s_num[sub][np] = num;
    s_den[sub][np] = den;
    __syncthreads();

    if (tid < 32) {
        int nn = grp * 32 + tid;
        if (nn < NPTS) {
            float nm = 0.f, dn = 0.f;
#pragma unroll
            for (int i = 0; i < 8; i++) { nm += s_num[i][tid]; dn += s_den[i][tid]; }
            float ttn0 = TT0 + (float)nn * DT;
            float rn = nm / dn;
            float x = fmaf(rn, cosf(ttn0), 256.0f);
            float y = fmaf(rn, sinf(ttn0), 256.0f);
            int idx; float xo;
            if (c == 0) { idx = nn;       xo = x; }
            else        { idx = 399 - nn; xo = 512.0f - x; }
            out[((size_t)b * 400 + idx) * 2 + 0] = xo;
            out[((size_t)b * 400 + idx) * 2 + 1] = y;
        }
    }
}

extern "C" void kernel_launch(void* const* d_in, const int* in_sizes, int n_in,
                              void* d_out, int out_size) {
    const float4* in = (const float4*)d_in[0];
    float* out = (float*)d_out;

    kA_pass<<<4096, 256>>>(in);
    k3_merged<<<1024, 256>>>(in, out);
}